// round 11
// baseline (speedup 1.0000x reference)
#include <cuda_runtime.h>
#include <cstdint>

#define NT    16384
#define DIM   2048
#define NE    64
#define TT    128
#define DC    64
#define NCH   (DIM / DC)   // 32
#define XSTR  66
#define LSTR  66
#define GAP_THRESH 1e-4f

// w transposed k-major: g_wt[k][e], fp32, 512 KB (L2-resident)
__device__ __align__(16) float g_wt[DIM * NE];

__device__ __forceinline__ uint32_t smem_u32(const void* p) {
    uint32_t a;
    asm("{ .reg .u64 t; cvta.to.shared.u64 t, %1; cvt.u32.u64 %0, t; }" : "=r"(a) : "l"(p));
    return a;
}
__device__ __forceinline__ unsigned long long pack2(float a) {
    unsigned long long r;
    asm("mov.b64 %0, {%1,%1};" : "=l"(r) : "f"(a));
    return r;
}
__device__ __forceinline__ unsigned long long fma2(unsigned long long a,
                                                   unsigned long long b,
                                                   unsigned long long c) {
    unsigned long long d;
    asm("fma.rn.f32x2 %0, %1, %2, %3;" : "=l"(d) : "l"(a), "l"(b), "l"(c));
    return d;
}
#define CP16(sa, ga) \
    asm volatile("cp.async.ca.shared.global [%0], [%1], 16;" :: "r"(sa), "l"(ga))
#define CP_COMMIT() asm volatile("cp.async.commit_group;" ::: "memory")
#define CP_WAIT0()  asm volatile("cp.async.wait_group 0;" ::: "memory")

// ---- prep: transpose w -> g_wt[k][e] ----
__global__ __launch_bounds__(512) void prep_wt(const float* __restrict__ w) {
    const int idx = blockIdx.x * 512 + threadIdx.x;   // 32768 = 64e x 512 k4
    const int e = idx >> 9, k4 = idx & 511;
    float4 v = *reinterpret_cast<const float4*>(w + (size_t)e * DIM + k4 * 4);
    g_wt[(k4 * 4 + 0) * NE + e] = v.x;
    g_wt[(k4 * 4 + 1) * NE + e] = v.y;
    g_wt[(k4 * 4 + 2) * NE + e] = v.z;
    g_wt[(k4 * 4 + 3) * NE + e] = v.w;
}

// ---- main ----
__global__ __launch_bounds__(512, 1)
void router_ffma(const float* __restrict__ x, const float* __restrict__ w,
                 float* __restrict__ out)
{
    __shared__ __align__(16) float xs[TT * XSTR];        // 33792 B, reused as logits
    __shared__ __align__(16) float ws[2][DC * NE];       // 2 x 16 KB (cp.async dst)
    __shared__ int   s_cnt;
    __shared__ int   s_list[TT];
    __shared__ float s_part[8][64];
    __shared__ float s_lg[66];

    const int tid  = threadIdx.x;
    const int lane = tid & 31;
    const int wp   = tid >> 5;        // 0..15
    const int th   = wp >> 3;         // token half (x64)
    const int we   = (wp & 7) * 8;    // expert octet
    const int tok0 = blockIdx.x * TT;

    if (tid == 0) s_cnt = 0;

    // x stager: row = tid>>2, 16 k per thread
    const int xtok = tid >> 2, xkq = (tid & 3) * 16;
    const float* xg = x + (size_t)(tok0 + xtok) * DIM + xkq;
    float* xdst = xs + xtok * XSTR + xkq;

    float4 rx[4];
    auto loadX = [&](int c) {
#pragma unroll
        for (int i = 0; i < 4; i++)
            rx[i] = *reinterpret_cast<const float4*>(xg + c * DC + i * 4);
    };

    const uint32_t wsu = smem_u32(ws);
    auto issueW = [&](int c, int b) {
        const char* src = reinterpret_cast<const char*>(g_wt) + (size_t)c * DC * NE * 4;
#pragma unroll
        for (int it = 0; it < 2; it++) {
            int i = tid + 512 * it;                 // 0..1023 x 16B = 16 KB
            CP16(wsu + (uint32_t)(b * DC * NE * 4 + i * 16), src + i * 16);
        }
    };

    unsigned long long acc[2][4];
#pragma unroll
    for (int c = 0; c < 2; c++)
#pragma unroll
        for (int p = 0; p < 4; p++) acc[c][p] = 0ull;

    issueW(0, 0);
    CP_COMMIT();
    loadX(0);

    const float* xr0 = xs + (64 * th + lane) * XSTR;
    const float* xr1 = xr0 + 32 * XSTR;

    for (int c = 0; c < NCH; c++) {
        const int b = c & 1;
        __syncthreads();                    // prev compute done -> xs free
        // stage x (STS.64, conflict-light; stride 66 keeps LDS.64 reads clean)
#pragma unroll
        for (int i = 0; i < 4; i++) {
            *reinterpret_cast<float2*>(xdst + i * 4)     = make_float2(rx[i].x, rx[i].y);
            *reinterpret_cast<float2*>(xdst + i * 4 + 2) = make_float2(rx[i].z, rx[i].w);
        }
        CP_WAIT0();                         // this chunk's w landed
        __syncthreads();                    // xs + ws[b] visible

        if (c + 1 < NCH) {
            issueW(c + 1, b ^ 1);           // fill other buffer during compute
            CP_COMMIT();
            loadX(c + 1);
        }

        const float* wb = ws[b];
#pragma unroll 4
        for (int k = 0; k < DC; k += 2) {
            float2 a0 = *reinterpret_cast<const float2*>(xr0 + k);
            float2 a1 = *reinterpret_cast<const float2*>(xr1 + k);
            ulonglong2 b01 = *reinterpret_cast<const ulonglong2*>(wb + k * NE + we);
            ulonglong2 b23 = *reinterpret_cast<const ulonglong2*>(wb + k * NE + we + 4);
            ulonglong2 d01 = *reinterpret_cast<const ulonglong2*>(wb + (k + 1) * NE + we);
            ulonglong2 d23 = *reinterpret_cast<const ulonglong2*>(wb + (k + 1) * NE + we + 4);
            unsigned long long A;
            A = pack2(a0.x);
            acc[0][0] = fma2(A, b01.x, acc[0][0]);
            acc[0][1] = fma2(A, b01.y, acc[0][1]);
            acc[0][2] = fma2(A, b23.x, acc[0][2]);
            acc[0][3] = fma2(A, b23.y, acc[0][3]);
            A = pack2(a1.x);
            acc[1][0] = fma2(A, b01.x, acc[1][0]);
            acc[1][1] = fma2(A, b01.y, acc[1][1]);
            acc[1][2] = fma2(A, b23.x, acc[1][2]);
            acc[1][3] = fma2(A, b23.y, acc[1][3]);
            A = pack2(a0.y);
            acc[0][0] = fma2(A, d01.x, acc[0][0]);
            acc[0][1] = fma2(A, d01.y, acc[0][1]);
            acc[0][2] = fma2(A, d23.x, acc[0][2]);
            acc[0][3] = fma2(A, d23.y, acc[0][3]);
            A = pack2(a1.y);
            acc[1][0] = fma2(A, d01.x, acc[1][0]);
            acc[1][1] = fma2(A, d01.y, acc[1][1]);
            acc[1][2] = fma2(A, d23.x, acc[1][2]);
            acc[1][3] = fma2(A, d23.y, acc[1][3]);
        }
    }

    // ---- logits -> smem (xs region) ----
    __syncthreads();
    float* ls = xs;
    {
#pragma unroll
        for (int cc = 0; cc < 2; cc++) {
            const int tok = 64 * th + lane + 32 * cc;
#pragma unroll
            for (int p = 0; p < 4; p++)
                *reinterpret_cast<unsigned long long*>(ls + tok * LSTR + we + 2 * p)
                    = acc[cc][p];
        }
    }
    __syncthreads();

    float* outp = out;
    float* outi = out + (size_t)NT * 8;
    float* outa = out + (size_t)NT * 16;

    const int tbase = wp * 8;
#pragma unroll 1
    for (int tt = 0; tt < 8; tt++) {
        const int tok = tbase + tt;
        float2 v = *reinterpret_cast<const float2*>(ls + tok * LSTR + 2 * lane);

        float m = fmaxf(v.x, v.y);
#pragma unroll
        for (int o = 16; o > 0; o >>= 1)
            m = fmaxf(m, __shfl_xor_sync(0xffffffffu, m, o));

        float e0 = expf(v.x - m);
        float e1 = expf(v.y - m);
        float ssum = e0 + e1;
#pragma unroll
        for (int o = 16; o > 0; o >>= 1)
            ssum += __shfl_xor_sync(0xffffffffu, ssum, o);

        float inv = 1.0f / ssum;
        float p0 = e0 * inv, p1 = e1 * inv;

        const int gtok = tok0 + tok;
        *reinterpret_cast<float2*>(outa + (size_t)gtok * 64 + 2 * lane)
            = make_float2(p0, p1);

        // top-9 on logits, min adjacent gap -> flag near-ties
        float c0 = v.x, c1 = v.y;
        int i0 = 2 * lane, i1 = 2 * lane + 1;
        float tv = 0.0f, tsum = 0.0f, prevv = 0.0f, mingap = 1e30f;
        int ti = 0;
#pragma unroll
        for (int r = 0; r < 9; r++) {
            float bv; int bi;
            if (c0 > c1 || (c0 == c1 && i0 < i1)) { bv = c0; bi = i0; }
            else                                  { bv = c1; bi = i1; }
#pragma unroll
            for (int o = 16; o > 0; o >>= 1) {
                float ov = __shfl_xor_sync(0xffffffffu, bv, o);
                int   oi = __shfl_xor_sync(0xffffffffu, bi, o);
                if (ov > bv || (ov == bv && oi < bi)) { bv = ov; bi = oi; }
            }
            if (r > 0) mingap = fminf(mingap, prevv - bv);
            prevv = bv;
            if (r < 8) {
                float bp = expf(bv - m) * inv;
                tsum += bp;
                if (lane == r) { tv = bp; ti = bi; }
                if (bi == i0)      c0 = -1e30f;
                else if (bi == i1) c1 = -1e30f;
            }
        }
        if (lane < 8) {
            outp[(size_t)gtok * 8 + lane] = tv / (tsum + 1e-9f);
            outi[(size_t)gtok * 8 + lane] = (float)ti;
        }
        if (lane == 0 && mingap < GAP_THRESH) {
            int pos = atomicAdd(&s_cnt, 1);
            s_list[pos] = gtok;
        }
    }

    // ---- inline exact fp32 fixup for flagged tokens ----
    __syncthreads();
    const int nfix = s_cnt;
    for (int i = 0; i < nfix; i++) {
        const int tok = s_list[i];
        const int e = tid & 63, kp = tid >> 6;        // 8 k-parts of 256
        const float* xr = x + (size_t)tok * DIM + kp * 256;
        const float* wr = w + (size_t)e * DIM + kp * 256;
        float s = 0.0f;
#pragma unroll 4
        for (int k = 0; k < 256; k += 4) {
            float4 xv = *reinterpret_cast<const float4*>(xr + k);
            float4 wv = *reinterpret_cast<const float4*>(wr + k);
            s = fmaf(xv.x, wv.x, s);
            s = fmaf(xv.y, wv.y, s);
            s = fmaf(xv.z, wv.z, s);
            s = fmaf(xv.w, wv.w, s);
        }
        s_part[kp][e] = s;
        __syncthreads();
        if (tid < 64) {
            float a = (s_part[0][tid] + s_part[1][tid]) + (s_part[2][tid] + s_part[3][tid]);
            float b = (s_part[4][tid] + s_part[5][tid]) + (s_part[6][tid] + s_part[7][tid]);
            s_lg[tid] = a + b;
        }
        __syncthreads();

        if (tid < 32) {
            float2 v = make_float2(s_lg[2 * lane], s_lg[2 * lane + 1]);

            float m = fmaxf(v.x, v.y);
#pragma unroll
            for (int o = 16; o > 0; o >>= 1)
                m = fmaxf(m, __shfl_xor_sync(0xffffffffu, m, o));

            float e0 = expf(v.x - m);
            float e1 = expf(v.y - m);
            float ssum = e0 + e1;
#pragma unroll
            for (int o = 16; o > 0; o >>= 1)
                ssum += __shfl_xor_sync(0xffffffffu, ssum, o);

            float inv = 1.0f / ssum;
            float p0 = e0 * inv, p1 = e1 * inv;

            *reinterpret_cast<float2*>(outa + (size_t)tok * 64 + 2 * lane)
                = make_float2(p0, p1);

            float c0 = p0, c1 = p1;
            int i0 = 2 * lane, i1 = 2 * lane + 1;
            float tv = 0.0f, tsum = 0.0f;
            int ti = 0;
#pragma unroll
            for (int r = 0; r < 8; r++) {
                float bv; int bi;
                if (c0 > c1 || (c0 == c1 && i0 < i1)) { bv = c0; bi = i0; }
                else                                  { bv = c1; bi = i1; }
#pragma unroll
                for (int o = 16; o > 0; o >>= 1) {
                    float ov = __shfl_xor_sync(0xffffffffu, bv, o);
                    int   oi = __shfl_xor_sync(0xffffffffu, bi, o);
                    if (ov > bv || (ov == bv && oi < bi)) { bv = ov; bi = oi; }
                }
                tsum += bv;
                if (lane == r) { tv = bv; ti = bi; }
                if (bi == i0)      c0 = -1.0f;
                else if (bi == i1) c1 = -1.0f;
            }
            if (lane < 8) {
                outp[(size_t)tok * 8 + lane] = tv / (tsum + 1e-9f);
                outi[(size_t)tok * 8 + lane] = (float)ti;
            }
        }
        __syncthreads();
    }
}

extern "C" void kernel_launch(void* const* d_in, const int* in_sizes, int n_in,
                              void* d_out, int out_size)
{
    (void)in_sizes; (void)n_in; (void)out_size;
    const float* x = (const float*)d_in[0];
    const float* w = (const float*)d_in[1];
    prep_wt<<<64, 512>>>(w);
    router_ffma<<<NT / TT, 512>>>(x, w, (float*)d_out);
}

// round 12
// speedup vs baseline: 1.0193x; 1.0193x over previous
#include <cuda_runtime.h>
#include <cstdint>

#define NT    16384
#define DIM   2048
#define NE    64
#define TT    128
#define DC    32
#define NCH   (DIM / DC)   // 64
#define XSTR  33
#define LSTR  66
#define GAP_THRESH 1e-4f

// w transposed k-major: g_wt[k][e], fp32, 512 KB (L2-resident)
__device__ __align__(16) float g_wt[DIM * NE];

__device__ __forceinline__ uint32_t smem_u32(const void* p) {
    uint32_t a;
    asm("{ .reg .u64 t; cvta.to.shared.u64 t, %1; cvt.u32.u64 %0, t; }" : "=r"(a) : "l"(p));
    return a;
}
__device__ __forceinline__ unsigned long long pack2(float a) {
    unsigned long long r;
    asm("mov.b64 %0, {%1,%1};" : "=l"(r) : "f"(a));
    return r;
}
__device__ __forceinline__ unsigned long long fma2(unsigned long long a,
                                                   unsigned long long b,
                                                   unsigned long long c) {
    unsigned long long d;
    asm("fma.rn.f32x2 %0, %1, %2, %3;" : "=l"(d) : "l"(a), "l"(b), "l"(c));
    return d;
}
#define CP16(sa, ga) \
    asm volatile("cp.async.ca.shared.global [%0], [%1], 16;" :: "r"(sa), "l"(ga))
#define CP_COMMIT() asm volatile("cp.async.commit_group;" ::: "memory")
#define CP_WAIT0()  asm volatile("cp.async.wait_group 0;" ::: "memory")

// ---- prep: transpose w -> g_wt[k][e] ----
__global__ __launch_bounds__(512) void prep_wt(const float* __restrict__ w) {
    const int idx = blockIdx.x * 512 + threadIdx.x;   // 32768 = 64e x 512 k4
    const int e = idx >> 9, k4 = idx & 511;
    float4 v = *reinterpret_cast<const float4*>(w + (size_t)e * DIM + k4 * 4);
    g_wt[(k4 * 4 + 0) * NE + e] = v.x;
    g_wt[(k4 * 4 + 1) * NE + e] = v.y;
    g_wt[(k4 * 4 + 2) * NE + e] = v.z;
    g_wt[(k4 * 4 + 3) * NE + e] = v.w;
}

// ---- main ----
__global__ __launch_bounds__(512, 1)
void router_ffma(const float* __restrict__ x, const float* __restrict__ w,
                 float* __restrict__ out)
{
    // union area: GEMM = xs[4224] + ws[2][1024 u64? no: 2*2048 floats]; logits = 128*66
    __shared__ __align__(16) float smem_all[TT * LSTR];   // 8448 floats = 33792 B
    __shared__ int   s_cnt;
    __shared__ int   s_list[TT];
    __shared__ float s_part[8][64];
    __shared__ float s_lg[66];

    float* xs = smem_all;                       // [128][33] = 4224 floats
    float* ws = smem_all + TT * XSTR;           // [2][32*64] = 4096 floats

    const int tid  = threadIdx.x;
    const int lane = tid & 31;
    const int wp   = tid >> 5;        // 0..15
    const int th   = wp >> 3;         // token half (x64)
    const int we   = (wp & 7) * 8;    // expert octet
    const int tok0 = blockIdx.x * TT;

    if (tid == 0) s_cnt = 0;

    // x stager: row = tid>>2, 8 k per thread per chunk
    const int xtok = tid >> 2, xkq = (tid & 3) * 8;
    const float* xg = x + (size_t)(tok0 + xtok) * DIM + xkq;
    float* xdst = xs + xtok * XSTR + xkq;

    float4 rx[2];
    auto loadX = [&](int c) {
        rx[0] = *reinterpret_cast<const float4*>(xg + c * DC);
        rx[1] = *reinterpret_cast<const float4*>(xg + c * DC + 4);
    };

    const uint32_t wsu = smem_u32(ws);
    auto issueW = [&](int c, int b) {
        // one 16B cp.async per thread: 512*16 = 8192 B = DC*NE floats
        const char* src = reinterpret_cast<const char*>(g_wt) + (size_t)c * DC * NE * 4;
        CP16(wsu + (uint32_t)(b * DC * NE * 4 + tid * 16), src + tid * 16);
    };

    unsigned long long acc[2][4];
#pragma unroll
    for (int c = 0; c < 2; c++)
#pragma unroll
        for (int p = 0; p < 4; p++) acc[c][p] = 0ull;

    issueW(0, 0);
    CP_COMMIT();
    loadX(0);

    const float* xr0 = xs + (64 * th + lane) * XSTR;        // token th*64+lane
    const float* xr1 = xr0 + 32 * XSTR;                     // +32

    for (int c = 0; c < NCH; c++) {
        const int b = c & 1;
        __syncthreads();                    // prev compute done -> xs free
        // scalar stores, conflict-free: bank = (row + kq + j) mod 32 distinct per warp
#pragma unroll
        for (int j = 0; j < 4; j++) xdst[j]     = (&rx[0].x)[j];
#pragma unroll
        for (int j = 0; j < 4; j++) xdst[4 + j] = (&rx[1].x)[j];
        CP_WAIT0();                         // this chunk's w landed
        __syncthreads();                    // xs + ws[b] visible

        if (c + 1 < NCH) {
            issueW(c + 1, b ^ 1);           // fill other buffer during compute
            CP_COMMIT();
            loadX(c + 1);
        }

        const float* wb = ws + b * DC * NE;
#pragma unroll 8
        for (int k = 0; k < DC; k++) {
            unsigned long long A0 = pack2(xr0[k]);          // bank=(lane+k)%32
            unsigned long long A1 = pack2(xr1[k]);
            const float* wk = wb + k * NE + we;             // warp-uniform
            ulonglong2 b01 = *reinterpret_cast<const ulonglong2*>(wk);
            ulonglong2 b23 = *reinterpret_cast<const ulonglong2*>(wk + 4);
            acc[0][0] = fma2(A0, b01.x, acc[0][0]);
            acc[0][1] = fma2(A0, b01.y, acc[0][1]);
            acc[0][2] = fma2(A0, b23.x, acc[0][2]);
            acc[0][3] = fma2(A0, b23.y, acc[0][3]);
            acc[1][0] = fma2(A1, b01.x, acc[1][0]);
            acc[1][1] = fma2(A1, b01.y, acc[1][1]);
            acc[1][2] = fma2(A1, b23.x, acc[1][2]);
            acc[1][3] = fma2(A1, b23.y, acc[1][3]);
        }
    }

    // ---- logits -> smem_all as [128][66] ----
    __syncthreads();                        // all compute done before overwrite
    float* ls = smem_all;
#pragma unroll
    for (int cc = 0; cc < 2; cc++) {
        const int tok = 64 * th + lane + 32 * cc;
#pragma unroll
        for (int p = 0; p < 4; p++)
            *reinterpret_cast<unsigned long long*>(ls + tok * LSTR + we + 2 * p)
                = acc[cc][p];
    }
    __syncthreads();

    float* outp = out;
    float* outi = out + (size_t)NT * 8;
    float* outa = out + (size_t)NT * 16;

    const int tbase = wp * 8;
#pragma unroll 1
    for (int tt = 0; tt < 8; tt++) {
        const int tok = tbase + tt;
        float2 v = *reinterpret_cast<const float2*>(ls + tok * LSTR + 2 * lane);

        float m = fmaxf(v.x, v.y);
#pragma unroll
        for (int o = 16; o > 0; o >>= 1)
            m = fmaxf(m, __shfl_xor_sync(0xffffffffu, m, o));

        float e0 = expf(v.x - m);
        float e1 = expf(v.y - m);
        float ssum = e0 + e1;
#pragma unroll
        for (int o = 16; o > 0; o >>= 1)
            ssum += __shfl_xor_sync(0xffffffffu, ssum, o);

        float inv = 1.0f / ssum;
        float p0 = e0 * inv, p1 = e1 * inv;

        const int gtok = tok0 + tok;
        *reinterpret_cast<float2*>(outa + (size_t)gtok * 64 + 2 * lane)
            = make_float2(p0, p1);

        // top-9 on logits, min adjacent gap -> flag near-ties
        float c0 = v.x, c1 = v.y;
        int i0 = 2 * lane, i1 = 2 * lane + 1;
        float tv = 0.0f, tsum = 0.0f, prevv = 0.0f, mingap = 1e30f;
        int ti = 0;
#pragma unroll
        for (int r = 0; r < 9; r++) {
            float bv; int bi;
            if (c0 > c1 || (c0 == c1 && i0 < i1)) { bv = c0; bi = i0; }
            else                                  { bv = c1; bi = i1; }
#pragma unroll
            for (int o = 16; o > 0; o >>= 1) {
                float ov = __shfl_xor_sync(0xffffffffu, bv, o);
                int   oi = __shfl_xor_sync(0xffffffffu, bi, o);
                if (ov > bv || (ov == bv && oi < bi)) { bv = ov; bi = oi; }
            }
            if (r > 0) mingap = fminf(mingap, prevv - bv);
            prevv = bv;
            if (r < 8) {
                float bp = expf(bv - m) * inv;
                tsum += bp;
                if (lane == r) { tv = bp; ti = bi; }
                if (bi == i0)      c0 = -1e30f;
                else if (bi == i1) c1 = -1e30f;
            }
        }
        if (lane < 8) {
            outp[(size_t)gtok * 8 + lane] = tv / (tsum + 1e-9f);
            outi[(size_t)gtok * 8 + lane] = (float)ti;
        }
        if (lane == 0 && mingap < GAP_THRESH) {
            int pos = atomicAdd(&s_cnt, 1);
            s_list[pos] = gtok;
        }
    }

    // ---- inline exact fp32 fixup for flagged tokens ----
    __syncthreads();
    const int nfix = s_cnt;
    for (int i = 0; i < nfix; i++) {
        const int tok = s_list[i];
        const int e = tid & 63, kp = tid >> 6;        // 8 k-parts of 256
        const float* xr = x + (size_t)tok * DIM + kp * 256;
        const float* wr = w + (size_t)e * DIM + kp * 256;
        float s = 0.0f;
#pragma unroll 4
        for (int k = 0; k < 256; k += 4) {
            float4 xv = *reinterpret_cast<const float4*>(xr + k);
            float4 wv = *reinterpret_cast<const float4*>(wr + k);
            s = fmaf(xv.x, wv.x, s);
            s = fmaf(xv.y, wv.y, s);
            s = fmaf(xv.z, wv.z, s);
            s = fmaf(xv.w, wv.w, s);
        }
        s_part[kp][e] = s;
        __syncthreads();
        if (tid < 64) {
            float a = (s_part[0][tid] + s_part[1][tid]) + (s_part[2][tid] + s_part[3][tid]);
            float b = (s_part[4][tid] + s_part[5][tid]) + (s_part[6][tid] + s_part[7][tid]);
            s_lg[tid] = a + b;
        }
        __syncthreads();

        if (tid < 32) {
            float2 v = make_float2(s_lg[2 * lane], s_lg[2 * lane + 1]);

            float m = fmaxf(v.x, v.y);
#pragma unroll
            for (int o = 16; o > 0; o >>= 1)
                m = fmaxf(m, __shfl_xor_sync(0xffffffffu, m, o));

            float e0 = expf(v.x - m);
            float e1 = expf(v.y - m);
            float ssum = e0 + e1;
#pragma unroll
            for (int o = 16; o > 0; o >>= 1)
                ssum += __shfl_xor_sync(0xffffffffu, ssum, o);

            float inv = 1.0f / ssum;
            float p0 = e0 * inv, p1 = e1 * inv;

            *reinterpret_cast<float2*>(outa + (size_t)tok * 64 + 2 * lane)
                = make_float2(p0, p1);

            float c0 = p0, c1 = p1;
            int i0 = 2 * lane, i1 = 2 * lane + 1;
            float tv = 0.0f, tsum = 0.0f;
            int ti = 0;
#pragma unroll
            for (int r = 0; r < 8; r++) {
                float bv; int bi;
                if (c0 > c1 || (c0 == c1 && i0 < i1)) { bv = c0; bi = i0; }
                else                                  { bv = c1; bi = i1; }
#pragma unroll
                for (int o = 16; o > 0; o >>= 1) {
                    float ov = __shfl_xor_sync(0xffffffffu, bv, o);
                    int   oi = __shfl_xor_sync(0xffffffffu, bi, o);
                    if (ov > bv || (ov == bv && oi < bi)) { bv = ov; bi = oi; }
                }
                tsum += bv;
                if (lane == r) { tv = bv; ti = bi; }
                if (bi == i0)      c0 = -1.0f;
                else if (bi == i1) c1 = -1.0f;
            }
            if (lane < 8) {
                outp[(size_t)tok * 8 + lane] = tv / (tsum + 1e-9f);
                outi[(size_t)tok * 8 + lane] = (float)ti;
            }
        }
        __syncthreads();
    }
}

extern "C" void kernel_launch(void* const* d_in, const int* in_sizes, int n_in,
                              void* d_out, int out_size)
{
    (void)in_sizes; (void)n_in; (void)out_size;
    const float* x = (const float*)d_in[0];
    const float* w = (const float*)d_in[1];
    prep_wt<<<64, 512>>>(w);
    router_ffma<<<NT / TT, 512>>>(x, w, (float*)d_out);
}

// round 13
// speedup vs baseline: 1.3740x; 1.3481x over previous
#include <cuda_runtime.h>
#include <cuda_fp16.h>
#include <cstdint>

#define NT    16384
#define DIM   2048
#define NE    64
#define TT    128            // tokens per CTA
#define KCH   128            // k per chunk
#define NCHK  16
#define KS_PER_CH 8
#define NKS   128
#define LSTR  66
#define GAP_THRESH 1e-4f

// g_w: [ch(16)][plane(2)][ks(8)][3072B], ks-block = 8 n8-tiles x 384B,
// tile = 8 rows x 48B (k0-7 @ +0, k8-15 @ +16, 16B pad)
#define KSB   3072
#define PO    (8 * KSB)              // 24576 (plane offset within chunk)
#define STG   (2 * PO)               // 49152 per chunk
#define SMEM_TOTAL (2 * STG)         // 98304 (2 stages; logits reuse)

__device__ __align__(16) unsigned char g_w[NCHK * STG];   // 768 KB

__device__ __forceinline__ uint32_t smem_u32(const void* p) {
    uint32_t a;
    asm("{ .reg .u64 t; cvta.to.shared.u64 t, %1; cvt.u32.u64 %0, t; }" : "=r"(a) : "l"(p));
    return a;
}
__device__ __forceinline__ void split2(float2 v, uint32_t& h, uint32_t& m) {
    __half2 hh = __float22half2_rn(v);
    float2 hf = __half22float2(hh);
    __half2 mm = __floats2half2_rn(v.x - hf.x, v.y - hf.y);
    h = *reinterpret_cast<uint32_t*>(&hh);
    m = *reinterpret_cast<uint32_t*>(&mm);
}
__device__ __forceinline__ void ldm4(uint32_t addr, uint32_t& r0, uint32_t& r1,
                                     uint32_t& r2, uint32_t& r3) {
    asm volatile("ldmatrix.sync.aligned.m8n8.x4.shared.b16 {%0,%1,%2,%3}, [%4];"
                 : "=r"(r0), "=r"(r1), "=r"(r2), "=r"(r3) : "r"(addr));
}
__device__ __forceinline__ void mma16816(float* c, const uint32_t* a,
                                         uint32_t b0, uint32_t b1) {
    asm volatile("mma.sync.aligned.m16n8k16.row.col.f32.f16.f16.f32 "
                 "{%0,%1,%2,%3}, {%4,%5,%6,%7}, {%8,%9}, {%0,%1,%2,%3};"
                 : "+f"(c[0]), "+f"(c[1]), "+f"(c[2]), "+f"(c[3])
                 : "r"(a[0]), "r"(a[1]), "r"(a[2]), "r"(a[3]), "r"(b0), "r"(b1));
}
#define CP16(sa, ga) \
    asm volatile("cp.async.ca.shared.global [%0], [%1], 16;" :: "r"(sa), "l"(ga))
#define CP_COMMIT() asm volatile("cp.async.commit_group;" ::: "memory")
#define CP_WAIT0()  asm volatile("cp.async.wait_group 0;" ::: "memory")

// ---- prep: w (x256) -> fp16 h/m planes in R4 fragment geometry ----
__global__ __launch_bounds__(256) void prep_wf(const float* __restrict__ w) {
    const int idx = blockIdx.x * 256 + threadIdx.x;     // 16384 = 64e x 256 k8-groups
    const int e = idx >> 8;
    const int k = (idx & 255) * 8;
    float4 v0 = *reinterpret_cast<const float4*>(w + (size_t)e * DIM + k);
    float4 v1 = *reinterpret_cast<const float4*>(w + (size_t)e * DIM + k + 4);
    uint32_t h[4], m[4];
    split2(make_float2(v0.x * 256.0f, v0.y * 256.0f), h[0], m[0]);
    split2(make_float2(v0.z * 256.0f, v0.w * 256.0f), h[1], m[1]);
    split2(make_float2(v1.x * 256.0f, v1.y * 256.0f), h[2], m[2]);
    split2(make_float2(v1.z * 256.0f, v1.w * 256.0f), h[3], m[3]);
    const int ch = k >> 7, ks = (k >> 4) & 7, kk = k & 15;
    const size_t off = (size_t)ch * STG + (size_t)ks * KSB
                     + (e >> 3) * 384 + (e & 7) * 48 + (kk >> 3) * 16;
    *reinterpret_cast<uint4*>(g_w + off)      = make_uint4(h[0], h[1], h[2], h[3]);
    *reinterpret_cast<uint4*>(g_w + off + PO) = make_uint4(m[0], m[1], m[2], m[3]);
}

// ---- main (round-4 structure) ----
__global__ __launch_bounds__(512, 1)
void router_hmma(const float* __restrict__ x, const float* __restrict__ w,
                 float* __restrict__ out)
{
    extern __shared__ __align__(1024) char smem[];
    const uint32_t sb = smem_u32(smem);

    __shared__ int   s_cnt;
    __shared__ int   s_list[TT];
    __shared__ float s_part[8][64];
    __shared__ float s_lg[66];

    const int tid  = threadIdx.x;
    const int lane = tid & 31;
    const int wp   = tid >> 5;           // 0..15
    const int tok0 = blockIdx.x * TT;

    if (tid == 0) s_cnt = 0;

    const int qrow  = lane >> 2;
    const int qk    = (lane & 3) * 2;
    const int rbase = 16 * (wp & 7);
    const int jb    = (wp >> 3) * 4;

    // R4 ldmatrix lane-offset within a ks-block
    const int lm_m = lane >> 3, lm_i = lane & 7;
    const uint32_t lmoff = (uint32_t)((8 * (lm_m >> 1) + lm_i) * 48 + (lm_m & 1) * 16);

    const float* xa = x + (size_t)(tok0 + rbase + qrow) * DIM + qk;

    float acc[4][4];
#pragma unroll
    for (int j = 0; j < 4; j++)
#pragma unroll
        for (int q = 0; q < 4; q++) acc[j][q] = 0.0f;

    float2 pa[2][4];
    auto loadA = [&](int g, int s) {
        const float* p = xa + 16 * g;
        pa[s][0] = *reinterpret_cast<const float2*>(p);
        pa[s][1] = *reinterpret_cast<const float2*>(p + 8);
        pa[s][2] = *reinterpret_cast<const float2*>(p + 8 * DIM);
        pa[s][3] = *reinterpret_cast<const float2*>(p + 8 * DIM + 8);
    };
    loadA(0, 0);
    loadA(1, 1);

    auto issueW = [&](int ch, int b) {
        const unsigned char* src = g_w + (size_t)ch * STG;
#pragma unroll
        for (int it = 0; it < 6; it++) {
            int i = tid + 512 * it;                // 0..3071 x 16B = 49152B
            CP16(sb + (uint32_t)(b * STG + i * 16), src + i * 16);
        }
    };
    issueW(0, 0);
    CP_COMMIT();

    for (int ch = 0; ch < NCHK; ch++) {
        const int b = ch & 1;
        CP_WAIT0();
        __syncthreads();          // buf b staged; all warps done with buf b^1
        if (ch + 1 < NCHK) {
            issueW(ch + 1, b ^ 1);
            CP_COMMIT();
        }

#pragma unroll
        for (int ks = 0; ks < KS_PER_CH; ks++) {
            const int g = ch * KS_PER_CH + ks;
            const int s = g & 1;

            uint32_t ah[4], am[4];
            split2(pa[s][0], ah[0], am[0]);
            split2(pa[s][2], ah[1], am[1]);
            split2(pa[s][1], ah[2], am[2]);
            split2(pa[s][3], ah[3], am[3]);
            if (g + 2 < NKS) loadA(g + 2, s);

            const uint32_t bh_base = sb + (uint32_t)(b * STG + ks * KSB) + lmoff;
            uint32_t bh[8], bm[8];
            ldm4(bh_base + (jb + 0) * 384, bh[0], bh[1], bh[2], bh[3]);
            ldm4(bh_base + (jb + 2) * 384, bh[4], bh[5], bh[6], bh[7]);
#pragma unroll
            for (int j = 0; j < 4; j++)
                mma16816(acc[j], ah, bh[2 * j], bh[2 * j + 1]);
#pragma unroll
            for (int j = 0; j < 4; j++)
                mma16816(acc[j], am, bh[2 * j], bh[2 * j + 1]);
            ldm4(bh_base + PO + (jb + 0) * 384, bm[0], bm[1], bm[2], bm[3]);
            ldm4(bh_base + PO + (jb + 2) * 384, bm[4], bm[5], bm[6], bm[7]);
#pragma unroll
            for (int j = 0; j < 4; j++)
                mma16816(acc[j], ah, bm[2 * j], bm[2 * j + 1]);
        }
    }

    // ---- logits -> smem (undo x256 w scale) ----
    __syncthreads();
    float* ls = reinterpret_cast<float*>(smem);
    {
        const int r0 = rbase + qrow, r1 = r0 + 8;
        const int e00 = 32 * (wp >> 3) + qk;
#pragma unroll
        for (int j = 0; j < 4; j++) {
            int e = e00 + 8 * j;
            *reinterpret_cast<float2*>(ls + r0 * LSTR + e) =
                make_float2(acc[j][0] * 0.00390625f, acc[j][1] * 0.00390625f);
            *reinterpret_cast<float2*>(ls + r1 * LSTR + e) =
                make_float2(acc[j][2] * 0.00390625f, acc[j][3] * 0.00390625f);
        }
    }
    __syncthreads();

    float* outp = out;
    float* outi = out + (size_t)NT * 8;
    float* outa = out + (size_t)NT * 16;

    const int tbase = wp * 8;
#pragma unroll 1
    for (int tt = 0; tt < 8; tt++) {
        const int tok = tbase + tt;
        float2 v = *reinterpret_cast<const float2*>(ls + tok * LSTR + 2 * lane);

        float m = fmaxf(v.x, v.y);
#pragma unroll
        for (int o = 16; o > 0; o >>= 1)
            m = fmaxf(m, __shfl_xor_sync(0xffffffffu, m, o));

        float e0 = expf(v.x - m);
        float e1 = expf(v.y - m);
        float ssum = e0 + e1;
#pragma unroll
        for (int o = 16; o > 0; o >>= 1)
            ssum += __shfl_xor_sync(0xffffffffu, ssum, o);

        float inv = 1.0f / ssum;
        float p0 = e0 * inv, p1 = e1 * inv;

        const int gtok = tok0 + tok;
        *reinterpret_cast<float2*>(outa + (size_t)gtok * 64 + 2 * lane)
            = make_float2(p0, p1);

        // top-9 on logits, min adjacent gap -> flag near-ties
        float c0 = v.x, c1 = v.y;
        int i0 = 2 * lane, i1 = 2 * lane + 1;
        float tv = 0.0f, tsum = 0.0f, prevv = 0.0f, mingap = 1e30f;
        int ti = 0;
#pragma unroll
        for (int r = 0; r < 9; r++) {
            float bv; int bi;
            if (c0 > c1 || (c0 == c1 && i0 < i1)) { bv = c0; bi = i0; }
            else                                  { bv = c1; bi = i1; }
#pragma unroll
            for (int o = 16; o > 0; o >>= 1) {
                float ov = __shfl_xor_sync(0xffffffffu, bv, o);
                int   oi = __shfl_xor_sync(0xffffffffu, bi, o);
                if (ov > bv || (ov == bv && oi < bi)) { bv = ov; bi = oi; }
            }
            if (r > 0) mingap = fminf(mingap, prevv - bv);
            prevv = bv;
            if (r < 8) {
                float bp = expf(bv - m) * inv;
                tsum += bp;
                if (lane == r) { tv = bp; ti = bi; }
                if (bi == i0)      c0 = -1e30f;
                else if (bi == i1) c1 = -1e30f;
            }
        }
        if (lane < 8) {
            outp[(size_t)gtok * 8 + lane] = tv / (tsum + 1e-9f);
            outi[(size_t)gtok * 8 + lane] = (float)ti;
        }
        if (lane == 0 && mingap < GAP_THRESH) {
            int pos = atomicAdd(&s_cnt, 1);
            s_list[pos] = gtok;
        }
    }

    // ---- inline exact fp32 fixup ----
    __syncthreads();
    const int nfix = s_cnt;
    for (int i = 0; i < nfix; i++) {
        const int tok = s_list[i];
        const int e = tid & 63, kp = tid >> 6;        // 8 k-parts of 256
        const float* xr = x + (size_t)tok * DIM + kp * 256;
        const float* wr = w + (size_t)e * DIM + kp * 256;
        float s = 0.0f;
#pragma unroll 4
        for (int k = 0; k < 256; k += 4) {
            float4 xv = *reinterpret_cast<const float4*>(xr + k);
            float4 wv = *reinterpret_cast<const float4*>(wr + k);
            s = fmaf(xv.x, wv.x, s);
            s = fmaf(xv.y, wv.y, s);
            s = fmaf(xv.z, wv.z, s);
            s = fmaf(xv.w, wv.w, s);
        }
        s_part[kp][e] = s;
        __syncthreads();
        if (tid < 64) {
            float a = (s_part[0][tid] + s_part[1][tid]) + (s_part[2][tid] + s_part[3][tid]);
            float b = (s_part[4][tid] + s_part[5][tid]) + (s_part[6][tid] + s_part[7][tid]);
            s_lg[tid] = a + b;
        }
        __syncthreads();

        if (tid < 32) {
            float2 v = make_float2(s_lg[2 * lane], s_lg[2 * lane + 1]);

            float m = fmaxf(v.x, v.y);
#pragma unroll
            for (int o = 16; o > 0; o >>= 1)
                m = fmaxf(m, __shfl_xor_sync(0xffffffffu, m, o));

            float e0 = expf(v.x - m);
            float e1 = expf(v.y - m);
            float ssum = e0 + e1;
#pragma unroll
            for (int o = 16; o > 0; o >>= 1)
                ssum += __shfl_xor_sync(0xffffffffu, ssum, o);

            float inv = 1.0f / ssum;
            float p0 = e0 * inv, p1 = e1 * inv;

            *reinterpret_cast<float2*>(outa + (size_t)tok * 64 + 2 * lane)
                = make_float2(p0, p1);

            float c0 = p0, c1 = p1;
            int i0 = 2 * lane, i1 = 2 * lane + 1;
            float tv = 0.0f, tsum = 0.0f;
            int ti = 0;
#pragma unroll
            for (int r = 0; r < 8; r++) {
                float bv; int bi;
                if (c0 > c1 || (c0 == c1 && i0 < i1)) { bv = c0; bi = i0; }
                else                                  { bv = c1; bi = i1; }
#pragma unroll
                for (int o = 16; o > 0; o >>= 1) {
                    float ov = __shfl_xor_sync(0xffffffffu, bv, o);
                    int   oi = __shfl_xor_sync(0xffffffffu, bi, o);
                    if (ov > bv || (ov == bv && oi < bi)) { bv = ov; bi = oi; }
                }
                tsum += bv;
                if (lane == r) { tv = bv; ti = bi; }
                if (bi == i0)      c0 = -1.0f;
                else if (bi == i1) c1 = -1.0f;
            }
            if (lane < 8) {
                outp[(size_t)tok * 8 + lane] = tv / (tsum + 1e-9f);
                outi[(size_t)tok * 8 + lane] = (float)ti;
            }
        }
        __syncthreads();
    }
}

extern "C" void kernel_launch(void* const* d_in, const int* in_sizes, int n_in,
                              void* d_out, int out_size)
{
    (void)in_sizes; (void)n_in; (void)out_size;
    const float* x = (const float*)d_in[0];
    const float* w = (const float*)d_in[1];
    cudaFuncSetAttribute(router_hmma, cudaFuncAttributeMaxDynamicSharedMemorySize,
                         SMEM_TOTAL);
    prep_wf<<<64, 256>>>(w);
    router_hmma<<<NT / TT, 512, SMEM_TOTAL>>>(x, w, (float*)d_out);
}